// round 2
// baseline (speedup 1.0000x reference)
#include <cuda_runtime.h>

#define NN 8
#define CC 64
#define HH 128
#define WW 128
#define TAPS 9
#define STEPS 10
#define EPSV 1e-5f

// Scratch: normalized weights [n,9,h,w] and ping-pong x buffer [n,c,h,w]
__device__ float g_nw[(size_t)NN * TAPS * HH * WW];
__device__ float g_x[(size_t)NN * CC * HH * WW];

// ---------------------------------------------------------------------------
// Normalize: nw[n,t,h,w] = w[n,t,h,w] / (sum_t w + eps)
// ---------------------------------------------------------------------------
__global__ void mp_normalize_kernel(const float* __restrict__ wt) {
    int idx = blockIdx.x * blockDim.x + threadIdx.x;   // over N*H*W
    if (idx >= NN * HH * WW) return;
    int hw = idx % (HH * WW);
    int n  = idx / (HH * WW);
    const float* base = wt + (size_t)n * TAPS * HH * WW + hw;
    float v[TAPS];
    float s = EPSV;
#pragma unroll
    for (int t = 0; t < TAPS; t++) {
        v[t] = base[(size_t)t * HH * WW];
        s += v[t];
    }
    float inv = 1.0f / s;
    float* out = g_nw + (size_t)n * TAPS * HH * WW + hw;
#pragma unroll
    for (int t = 0; t < TAPS; t++)
        out[(size_t)t * HH * WW] = v[t] * inv;
}

// ---------------------------------------------------------------------------
// One propagation step: xout[n,c,h,w] = sum_t nw[n,t,h,w] * xin[n,c,h+di,w+dj]
// Each thread: one 8-wide w-strip at (n,h), 16 channels.
// Weights (9 taps x 8 px = 72 regs) loaded once, amortized over 16 channels.
// ---------------------------------------------------------------------------
#define SW 8
#define STRIPS (WW / SW)  // 16
#define CBLKS 4           // channel blocks
#define CPB (CC / CBLKS)  // 16 channels per thread

__global__ void __launch_bounds__(256) mp_step_kernel(
    const float* __restrict__ xin, float* __restrict__ xout)
{
    int tid = blockIdx.x * blockDim.x + threadIdx.x;
    const int total = CBLKS * NN * HH * STRIPS;   // 65536
    if (tid >= total) return;

    int s  = tid % STRIPS;
    int t1 = tid / STRIPS;
    int h  = t1 % HH;  t1 /= HH;
    int n  = t1 % NN;
    int cb = t1 / NN;
    int w0 = s * SW;

    // Load 9 taps x 8 pixels of normalized weights (2 aligned float4 per tap)
    float wv[TAPS][SW];
#pragma unroll
    for (int t = 0; t < TAPS; t++) {
        const float* wp = g_nw + (((size_t)n * TAPS + t) * HH + h) * WW + w0;
        float4 a = *(const float4*)wp;
        float4 b = *(const float4*)(wp + 4);
        wv[t][0] = a.x; wv[t][1] = a.y; wv[t][2] = a.z; wv[t][3] = a.w;
        wv[t][4] = b.x; wv[t][5] = b.y; wv[t][6] = b.z; wv[t][7] = b.w;
    }

    const size_t plane = (size_t)HH * WW;
    const float* xb = xin  + ((size_t)n * CC + cb * CPB) * plane;
    float*       ob = xout + ((size_t)n * CC + cb * CPB) * plane + (size_t)h * WW + w0;

    const bool hasL = (w0 > 0);
    const bool hasR = (w0 + SW < WW);
    const bool rmOK = (h > 0);
    const bool rpOK = (h + 1 < HH);

    for (int c = 0; c < CPB; c++) {
        const float* xc = xb + (size_t)c * plane + (size_t)h * WW + w0;
        float acc[SW];
#pragma unroll
        for (int k = 0; k < SW; k++) acc[k] = 0.f;

#pragma unroll
        for (int di = 0; di < 3; di++) {
            float v[SW + 2];
            bool rowOK = (di == 0) ? rmOK : (di == 2) ? rpOK : true;
            if (rowOK) {
                const float* row = xc + ((long)di - 1) * WW;
                float4 A = *(const float4*)row;
                float4 B = *(const float4*)(row + 4);
                v[1] = A.x; v[2] = A.y; v[3] = A.z; v[4] = A.w;
                v[5] = B.x; v[6] = B.y; v[7] = B.z; v[8] = B.w;
                v[0]      = hasL ? row[-1] : 0.f;
                v[SW + 1] = hasR ? row[SW] : 0.f;
            } else {
#pragma unroll
                for (int k = 0; k < SW + 2; k++) v[k] = 0.f;
            }
            const float* wL = wv[di * 3 + 0];
            const float* wC = wv[di * 3 + 1];
            const float* wR = wv[di * 3 + 2];
#pragma unroll
            for (int k = 0; k < SW; k++)
                acc[k] += wL[k] * v[k] + wC[k] * v[k + 1] + wR[k] * v[k + 2];
        }
        float* op = ob + (size_t)c * plane;
        *(float4*)(op)     = make_float4(acc[0], acc[1], acc[2], acc[3]);
        *(float4*)(op + 4) = make_float4(acc[4], acc[5], acc[6], acc[7]);
    }
}

// ---------------------------------------------------------------------------
// kernel_launch: normalize once, then 10 ping-pong steps ending in d_out.
// ---------------------------------------------------------------------------
extern "C" void kernel_launch(void* const* d_in, const int* in_sizes, int n_in,
                              void* d_out, int out_size) {
    (void)in_sizes; (void)n_in; (void)out_size;
    const float* input  = (const float*)d_in[0];
    const float* weight = (const float*)d_in[1];
    float* out = (float*)d_out;

    float* xscr = nullptr;
    cudaGetSymbolAddress((void**)&xscr, g_x);

    const int threads = 256;
    {
        int total = NN * HH * WW;
        mp_normalize_kernel<<<(total + threads - 1) / threads, threads>>>(weight);
    }

    const int totalStep = CBLKS * NN * HH * STRIPS;
    const int blocks = (totalStep + threads - 1) / threads;

    // 10 hops: in -> g_x -> out -> g_x -> out ... (step 10 ends in d_out)
    const float* src = input;
    for (int k = 1; k <= STEPS; k++) {
        float* dst = (k & 1) ? xscr : out;
        mp_step_kernel<<<blocks, threads>>>(src, dst);
        src = dst;
    }
}

// round 4
// speedup vs baseline: 1.3181x; 1.3181x over previous
#include <cuda_runtime.h>

#define NN 8
#define CC 64
#define HH 128
#define WW 128
#define TAPS 9
#define STEPS 10
#define EPSV 1e-5f

// Scratch: normalized weights [n,9,h,w] and ping-pong x buffer [n,c,h,w]
__device__ float g_nw[(size_t)NN * TAPS * HH * WW];
__device__ float g_x[(size_t)NN * CC * HH * WW];

// ---------------------------------------------------------------------------
// Normalize: nw[n,t,h,w] = w[n,t,h,w] / (sum_t w + eps)
// ---------------------------------------------------------------------------
__global__ void mp_normalize_kernel(const float* __restrict__ wt) {
    int idx = blockIdx.x * blockDim.x + threadIdx.x;   // over N*H*W
    if (idx >= NN * HH * WW) return;
    int hw = idx % (HH * WW);
    int n  = idx / (HH * WW);
    const float* base = wt + (size_t)n * TAPS * HH * WW + hw;
    float v[TAPS];
    float s = EPSV;
#pragma unroll
    for (int t = 0; t < TAPS; t++) {
        v[t] = base[(size_t)t * HH * WW];
        s += v[t];
    }
    float inv = 1.0f / s;
    float* out = g_nw + (size_t)n * TAPS * HH * WW + hw;
#pragma unroll
    for (int t = 0; t < TAPS; t++)
        out[(size_t)t * HH * WW] = v[t] * inv;
}

// ---------------------------------------------------------------------------
// One propagation step: xout[n,c,h,w] = sum_t nw[n,t,h,w] * xin[n,c,h+di,w+dj]
// Thread = (8-px strip, 8 channels). Lanes 0-15 of a warp are the 16 strips
// of one row -> halo pixels exchanged via warp shuffle (width 16), removing
// the scalar edge LDGs (each of which cost a full 32B L1 sector).
// ---------------------------------------------------------------------------
#define SW 8
#define STRIPS (WW / SW)  // 16
#define CBLKS 8           // channel blocks
#define CPB (CC / CBLKS)  // 8 channels per thread

__global__ void __launch_bounds__(256) mp_step_kernel(
    const float* __restrict__ xin, float* __restrict__ xout)
{
    int tid = blockIdx.x * blockDim.x + threadIdx.x;
    // total = CBLKS*NN*HH*STRIPS = 131072; grid sized exactly, no tail check
    int s  = tid & (STRIPS - 1);          // 0..15  == lane % 16
    int t1 = tid >> 4;
    int h  = t1 & (HH - 1);  t1 >>= 7;
    int n  = t1 & (NN - 1);
    int cb = t1 >> 3;
    int w0 = s * SW;

    // 9 taps x 8 px of normalized weights in registers (72 regs),
    // amortized over CPB=8 channels.
    float wv[TAPS][SW];
#pragma unroll
    for (int t = 0; t < TAPS; t++) {
        const float* wp = g_nw + (((size_t)n * TAPS + t) * HH + h) * WW + w0;
        float4 a = *(const float4*)wp;
        float4 b = *(const float4*)(wp + 4);
        wv[t][0] = a.x; wv[t][1] = a.y; wv[t][2] = a.z; wv[t][3] = a.w;
        wv[t][4] = b.x; wv[t][5] = b.y; wv[t][6] = b.z; wv[t][7] = b.w;
    }

    const size_t plane = (size_t)HH * WW;
    const float* xb = xin  + ((size_t)n * CC + cb * CPB) * plane + (size_t)h * WW + w0;
    float*       ob = xout + ((size_t)n * CC + cb * CPB) * plane + (size_t)h * WW + w0;

    const bool rmOK = (h > 0);
    const bool rpOK = (h + 1 < HH);

    for (int c = 0; c < CPB; c++) {
        const float* xc = xb + (size_t)c * plane;
        float acc[SW];
#pragma unroll
        for (int k = 0; k < SW; k++) acc[k] = 0.f;

#pragma unroll
        for (int di = 0; di < 3; di++) {
            bool rowOK = (di == 0) ? rmOK : (di == 2) ? rpOK : true;
            float v[SW + 2];
            if (rowOK) {
                const float* row = xc + ((long)di - 1) * WW;
                float4 A = *(const float4*)row;
                float4 B = *(const float4*)(row + 4);
                v[1] = A.x; v[2] = A.y; v[3] = A.z; v[4] = A.w;
                v[5] = B.x; v[6] = B.y; v[7] = B.z; v[8] = B.w;
            } else {
#pragma unroll
                for (int k = 1; k <= SW; k++) v[k] = 0.f;
            }
            // Halo via warp shuffle within the 16-lane row segment.
            // Left halo  = previous strip's last pixel (its v[8] = row[7]).
            // Right halo = next strip's first pixel  (its v[1] = row[0]).
            float l = __shfl_up_sync  (0xffffffffu, v[SW], 1, STRIPS);
            float r = __shfl_down_sync(0xffffffffu, v[1],  1, STRIPS);
            v[0]      = (s == 0)          ? 0.f : l;
            v[SW + 1] = (s == STRIPS - 1) ? 0.f : r;

            const float* wL = wv[di * 3 + 0];
            const float* wC = wv[di * 3 + 1];
            const float* wR = wv[di * 3 + 2];
#pragma unroll
            for (int k = 0; k < SW; k++)
                acc[k] += wL[k] * v[k] + wC[k] * v[k + 1] + wR[k] * v[k + 2];
        }
        float* op = ob + (size_t)c * plane;
        *(float4*)(op)     = make_float4(acc[0], acc[1], acc[2], acc[3]);
        *(float4*)(op + 4) = make_float4(acc[4], acc[5], acc[6], acc[7]);
    }
}

// ---------------------------------------------------------------------------
// kernel_launch: normalize once, then 10 ping-pong steps ending in d_out.
// ---------------------------------------------------------------------------
extern "C" void kernel_launch(void* const* d_in, const int* in_sizes, int n_in,
                              void* d_out, int out_size) {
    (void)in_sizes; (void)n_in; (void)out_size;
    const float* input  = (const float*)d_in[0];
    const float* weight = (const float*)d_in[1];
    float* out = (float*)d_out;

    float* xscr = nullptr;
    cudaGetSymbolAddress((void**)&xscr, g_x);

    const int threads = 256;
    {
        int total = NN * HH * WW;
        mp_normalize_kernel<<<(total + threads - 1) / threads, threads>>>(weight);
    }

    const int totalStep = CBLKS * NN * HH * STRIPS;  // 131072
    const int blocks = totalStep / threads;          // 512

    // 10 hops: in -> g_x -> out -> g_x -> out ... (step 10 ends in d_out)
    const float* src = input;
    for (int k = 1; k <= STEPS; k++) {
        float* dst = (k & 1) ? xscr : out;
        mp_step_kernel<<<blocks, threads>>>(src, dst);
        src = dst;
    }
}

// round 5
// speedup vs baseline: 1.6943x; 1.2854x over previous
#include <cuda_runtime.h>

#define NN 8
#define CC 64
#define HH 128
#define WW 128
#define TAPS 9
#define STEPS 10
#define EPSV 1e-5f

// Scratch: normalized weights [n,9,h,w] and ping-pong x buffer [n,c,h,w]
__device__ float g_nw[(size_t)NN * TAPS * HH * WW];
__device__ float g_x[(size_t)NN * CC * HH * WW];

// ---------------------------------------------------------------------------
// Normalize: nw[n,t,h,w] = w[n,t,h,w] / (sum_t w + eps)
// ---------------------------------------------------------------------------
__global__ void mp_normalize_kernel(const float* __restrict__ wt) {
    int idx = blockIdx.x * blockDim.x + threadIdx.x;   // over N*H*W
    if (idx >= NN * HH * WW) return;
    int hw = idx % (HH * WW);
    int n  = idx / (HH * WW);
    const float* base = wt + (size_t)n * TAPS * HH * WW + hw;
    float v[TAPS];
    float s = EPSV;
#pragma unroll
    for (int t = 0; t < TAPS; t++) {
        v[t] = base[(size_t)t * HH * WW];
        s += v[t];
    }
    float inv = 1.0f / s;
    float* out = g_nw + (size_t)n * TAPS * HH * WW + hw;
#pragma unroll
    for (int t = 0; t < TAPS; t++)
        out[(size_t)t * HH * WW] = v[t] * inv;
}

// ---------------------------------------------------------------------------
// One step: xout[n,c,h,w] = sum_t nw[n,t,h,w] * xin[n,c,h+di,w+dj]
// Thread = (4-px strip, 8 channels). One warp (32 lanes x 4 px) covers a full
// 128-px row -> halo via width-32 warp shuffle; lanes 0/31 are real image
// borders. SW=4 keeps the weight array at 36 regs so 4 blocks fit per SM
// (vs 2 at SW=8) -- the round-4 profile showed occupancy (21%) was the wall.
// ---------------------------------------------------------------------------
#define SW 4
#define STRIPS (WW / SW)  // 32 = warp width
#define CBLKS 8           // channel blocks
#define CPB (CC / CBLKS)  // 8 channels per thread

__global__ void __launch_bounds__(256, 4) mp_step_kernel(
    const float* __restrict__ xin, float* __restrict__ xout)
{
    int tid = blockIdx.x * blockDim.x + threadIdx.x;
    // total = CBLKS*NN*HH*STRIPS = 262144; grid sized exactly, no tail check
    int s  = tid & (STRIPS - 1);          // 0..31 == lane id
    int t1 = tid >> 5;
    int h  = t1 & (HH - 1);  t1 >>= 7;
    int n  = t1 & (NN - 1);
    int cb = t1 >> 3;
    int w0 = s * SW;

    // 9 taps x 4 px of normalized weights (36 regs), amortized over 8 channels
    float wv[TAPS][SW];
#pragma unroll
    for (int t = 0; t < TAPS; t++) {
        float4 a = *(const float4*)(g_nw + (((size_t)n * TAPS + t) * HH + h) * WW + w0);
        wv[t][0] = a.x; wv[t][1] = a.y; wv[t][2] = a.z; wv[t][3] = a.w;
    }

    const size_t plane = (size_t)HH * WW;
    const float* xb = xin  + ((size_t)n * CC + cb * CPB) * plane + (size_t)h * WW + w0;
    float*       ob = xout + ((size_t)n * CC + cb * CPB) * plane + (size_t)h * WW + w0;

    const bool rmOK = (h > 0);
    const bool rpOK = (h + 1 < HH);

    for (int c = 0; c < CPB; c++) {
        const float* xc = xb + (size_t)c * plane;
        float acc[SW];
#pragma unroll
        for (int k = 0; k < SW; k++) acc[k] = 0.f;

#pragma unroll
        for (int di = 0; di < 3; di++) {
            bool rowOK = (di == 0) ? rmOK : (di == 2) ? rpOK : true;
            float v[SW + 2];
            if (rowOK) {
                float4 A = *(const float4*)(xc + ((long)di - 1) * WW);
                v[1] = A.x; v[2] = A.y; v[3] = A.z; v[4] = A.w;
            } else {
                v[1] = v[2] = v[3] = v[4] = 0.f;
            }
            // Halo via full-warp shuffle: left = prev lane's last px,
            // right = next lane's first px. Lanes 0/31 are image borders.
            float l = __shfl_up_sync  (0xffffffffu, v[SW], 1);
            float r = __shfl_down_sync(0xffffffffu, v[1],  1);
            v[0]      = (s == 0)          ? 0.f : l;
            v[SW + 1] = (s == STRIPS - 1) ? 0.f : r;

            const float* wL = wv[di * 3 + 0];
            const float* wC = wv[di * 3 + 1];
            const float* wR = wv[di * 3 + 2];
#pragma unroll
            for (int k = 0; k < SW; k++)
                acc[k] += wL[k] * v[k] + wC[k] * v[k + 1] + wR[k] * v[k + 2];
        }
        *(float4*)(ob + (size_t)c * plane) = make_float4(acc[0], acc[1], acc[2], acc[3]);
    }
}

// ---------------------------------------------------------------------------
// kernel_launch: normalize once, then 10 ping-pong steps ending in d_out.
// ---------------------------------------------------------------------------
extern "C" void kernel_launch(void* const* d_in, const int* in_sizes, int n_in,
                              void* d_out, int out_size) {
    (void)in_sizes; (void)n_in; (void)out_size;
    const float* input  = (const float*)d_in[0];
    const float* weight = (const float*)d_in[1];
    float* out = (float*)d_out;

    float* xscr = nullptr;
    cudaGetSymbolAddress((void**)&xscr, g_x);

    const int threads = 256;
    {
        int total = NN * HH * WW;
        mp_normalize_kernel<<<(total + threads - 1) / threads, threads>>>(weight);
    }

    const int totalStep = CBLKS * NN * HH * STRIPS;  // 262144
    const int blocks = totalStep / threads;          // 1024

    // 10 hops: in -> g_x -> out -> g_x -> out ... (step 10 ends in d_out)
    const float* src = input;
    for (int k = 1; k <= STEPS; k++) {
        float* dst = (k & 1) ? xscr : out;
        mp_step_kernel<<<blocks, threads>>>(src, dst);
        src = dst;
    }
}